// round 11
// baseline (speedup 1.0000x reference)
#include <cuda_runtime.h>

#define NH 128
#define NI 64
#define NO 10
#define NB 128
#define S_MAX 2048

// 128 MiB scratch for the precomputed input projection xW[S,B,H].
__device__ __align__(16) float g_xw[(size_t)S_MAX * NB * NH];

// ---- packed f32x2 helpers (sm_100+ PTX) ----
__device__ __forceinline__ unsigned long long ffma2(unsigned long long a,
                                                    unsigned long long b,
                                                    unsigned long long c) {
    unsigned long long d;
    asm("fma.rn.f32x2 %0, %1, %2, %3;" : "=l"(d) : "l"(a), "l"(b), "l"(c));
    return d;
}
__device__ __forceinline__ unsigned long long addf2(unsigned long long a,
                                                    unsigned long long b) {
    unsigned long long d;
    asm("add.rn.f32x2 %0, %1, %2;" : "=l"(d) : "l"(a), "l"(b));
    return d;
}
__device__ __forceinline__ unsigned long long packf2(float lo, float hi) {
    unsigned long long r;
    asm("mov.b64 %0, {%1, %2};" : "=l"(r) : "f"(lo), "f"(hi));
    return r;
}
__device__ __forceinline__ float2 unpackf2(unsigned long long v) {
    float2 f;
    asm("mov.b64 {%0, %1}, %2;" : "=f"(f.x), "=f"(f.y) : "l"(v));
    return f;
}

// tanh(v) = 2/(1+exp(-2v)) - 1, branchless MUFU path:
// mul -> EX2 -> add -> RCP -> FMA (5 ops, ~44 serial cyc).
// v->+inf: ex2->0, rcp(1)=1, h=+1.  v->-inf: ex2->inf, rcp->0, h=-1.
// Numerics validated in R7 (rel_err 3.39e-7 over 2048 steps).
__device__ __forceinline__ float tanh_fast(float v) {
    float t = v * -2.8853900817779268f;  // -2*log2(e)
    float e, r;
    asm("ex2.approx.f32 %0, %1;" : "=f"(e) : "f"(t));
    asm("rcp.approx.f32 %0, %1;" : "=f"(r) : "f"(e + 1.0f));
    return fmaf(2.0f, r, -1.0f);
}

// ============================================================
// K1 (R7/R10 verbatim): xW[s,b,j] = x[s,b,:] @ Wxh[:,j] + bh[j]
// grid = (seq, 8): CTA handles 16 batch rows. block = 128.
// ============================================================
__global__ void __launch_bounds__(128, 1) xw_gemm_kernel(
    const float* __restrict__ x, const float* __restrict__ Wxh,
    const float* __restrict__ bh, int seq)
{
    const int s = blockIdx.x;
    const int bbase = blockIdx.y * 16;
    __shared__ __align__(16) float xs[16 * NI];  // 4 KB

    const float4* xin =
        reinterpret_cast<const float4*>(x + ((long long)s * NB + bbase) * NI);
    float4* xs4 = reinterpret_cast<float4*>(xs);
#pragma unroll
    for (int i = threadIdx.x; i < 16 * NI / 4; i += 128) xs4[i] = xin[i];

    const int j = threadIdx.x;

    unsigned long long w2[NI / 2];
#pragma unroll
    for (int m = 0; m < NI / 2; m++)
        w2[m] = packf2(Wxh[(2 * m) * NH + j], Wxh[(2 * m + 1) * NH + j]);
    const unsigned long long bias2 = packf2(bh[j], 0.0f);
    __syncthreads();

#pragma unroll
    for (int b = 0; b < 16; b++) {
        const ulonglong2* xr = reinterpret_cast<const ulonglong2*>(xs + b * NI);
        unsigned long long a0 = bias2, a1 = 0ull, a2 = 0ull, a3 = 0ull;
#pragma unroll
        for (int m = 0; m < NI / 4; m++) {
            ulonglong2 xv = xr[m];
            if (m & 1) { a2 = ffma2(xv.x, w2[2 * m], a2); a3 = ffma2(xv.y, w2[2 * m + 1], a3); }
            else       { a0 = ffma2(xv.x, w2[2 * m], a0); a1 = ffma2(xv.y, w2[2 * m + 1], a1); }
        }
        float2 f = unpackf2(addf2(addf2(a0, a1), addf2(a2, a3)));
        g_xw[((long long)s * NB + bbase + b) * NH + j] = f.x + f.y;
    }
}

// ============================================================
// K2: R10 scan verbatim EXCEPT tanh -> tanh_fast (single change).
// grid = NB (1 chain per CTA/SM), block = 128.
// Warp w owns columns [32w,32w+32) AND K-slice [32w,32w+32).
// ============================================================
__global__ void __launch_bounds__(NH, 1) rnn_scan_kernel(
    const float* __restrict__ Whh, const float* __restrict__ Why,
    const float* __restrict__ bh, const float* __restrict__ by,
    float* __restrict__ out, int seq)
{
    const int b   = blockIdx.x;
    const int tid = threadIdx.x;
    const int w   = tid >> 5;   // warp = K-slice index
    const int l   = tid & 31;

    // Weights: wp[c][kk] packs Whh[k][4l+c] for k-pair (32w+2kk, 32w+2kk+1).
    unsigned long long wp[4][16];
#pragma unroll
    for (int c = 0; c < 4; c++) {
        const int col = 4 * l + c;
#pragma unroll
        for (int kk = 0; kk < 16; kk++) {
            const int k = 32 * w + 2 * kk;
            wp[c][kk] = packf2(Whh[k * NH + col], Whh[(k + 1) * NH + col]);
        }
    }
    const float bias = bh[tid];

    __shared__ __align__(16) float hbuf[2][NH];        // parity-swapped h
    __shared__ __align__(16) float part[2][4][NH];     // double-buffered partials
    hbuf[0][tid] = 0.0f;

    // xw prefetch ring (depth 4) for OWN column tid
    const float* xwb = g_xw + (long long)b * NH + tid;
    float xq[4];
#pragma unroll
    for (int q = 0; q < 4; q++)
        xq[q] = (q < seq) ? xwb[(long long)q * NB * NH] : 0.0f;

    float* h_out = out + NB * NO;
    __syncthreads();

#pragma unroll 4
    for (int t = 0; t < seq; t++) {
        const int pb = t & 1;

        // ---- batched load of OWN warp's h slice (8 broadcast LDS.128) ----
        ulonglong2 hv[8];
        const ulonglong2* h2 =
            reinterpret_cast<const ulonglong2*>(&hbuf[pb][32 * w]);
#pragma unroll
        for (int m = 0; m < 8; m++) hv[m] = h2[m];

        // ---- 32-term partials for columns 4l..4l+3 (64 FFMA2) ----
        unsigned long long a0 = 0ull, a1 = 0ull, a2 = 0ull, a3 = 0ull;
#pragma unroll
        for (int m = 0; m < 8; m++) {
            a0 = ffma2(hv[m].x, wp[0][2 * m], a0);
            a0 = ffma2(hv[m].y, wp[0][2 * m + 1], a0);
            a1 = ffma2(hv[m].x, wp[1][2 * m], a1);
            a1 = ffma2(hv[m].y, wp[1][2 * m + 1], a1);
            a2 = ffma2(hv[m].x, wp[2][2 * m], a2);
            a2 = ffma2(hv[m].y, wp[2][2 * m + 1], a2);
            a3 = ffma2(hv[m].x, wp[3][2 * m], a3);
            a3 = ffma2(hv[m].y, wp[3][2 * m + 1], a3);
        }
        float2 f0 = unpackf2(a0), f1 = unpackf2(a1),
               f2 = unpackf2(a2), f3 = unpackf2(a3);
        float4 pr = make_float4(f0.x + f0.y, f1.x + f1.y,
                                f2.x + f2.y, f3.x + f3.y);
        *reinterpret_cast<float4*>(&part[pb][w][4 * l]) = pr;  // conflict-free

        // xw consume + refill (covers DRAM latency across 4 steps)
        const float xwv = xq[t & 3];
        if (t + 4 < seq) xq[t & 3] = xwb[(long long)(t + 4) * NB * NH];

        __syncthreads();

        // ---- reduce 4 partials for OWN column tid ----
        float v = ((part[pb][0][tid] + part[pb][1][tid]) +
                   (part[pb][2][tid] + part[pb][3][tid])) + xwv + bias;

        float h = tanh_fast(v);

        h_out[((long long)t * NB + b) * NH + tid] = h;  // coalesced 512 B
        hbuf[pb ^ 1][tid] = h;   // own-warp slice; next step reads own slice only
        __syncwarp();
    }

    __syncthreads();
    // ---- logits = h_last @ Why + by ----
    if (tid < NO) {
        float acc = by[tid];
#pragma unroll 8
        for (int k = 0; k < NH; k++)
            acc = fmaf(hbuf[seq & 1][k], Why[k * NO + tid], acc);
        out[b * NO + tid] = acc;
    }
}

extern "C" void kernel_launch(void* const* d_in, const int* in_sizes, int n_in,
                              void* d_out, int out_size) {
    const float* x   = (const float*)d_in[0];
    const float* Wxh = (const float*)d_in[1];
    const float* Whh = (const float*)d_in[2];
    const float* Why = (const float*)d_in[3];
    const float* bh  = (const float*)d_in[4];
    const float* by  = (const float*)d_in[5];
    float* out = (float*)d_out;

    int seq = in_sizes[0] / (NB * NI);  // 2048
    if (seq > S_MAX) seq = S_MAX;

    dim3 g1(seq, 8);
    xw_gemm_kernel<<<g1, 128>>>(x, Wxh, bh, seq);
    rnn_scan_kernel<<<NB, NH>>>(Whh, Why, bh, by, out, seq);
}